// round 8
// baseline (speedup 1.0000x reference)
#include <cuda_runtime.h>

#define TPB    256
#define NBINS  15
#define NCLS   16
#define NCELLS (NBINS * NCLS)   // 240
#define NBLK   1064             // 152 SMs * 7 blocks = exactly one wave

// Per-block per-cell partials, [cell][block] so the tail reads rows contiguously.
__device__ float        g_partials[NCELLS * NBLK];
__device__ unsigned int g_ticket = 0;

__device__ __forceinline__ void proc_pair(float2 xv, float2 tv,
                                          float (*acc)[NBINS][TPB], int tid) {
    float p0 = __fdividef(1.0f, 1.0f + __expf(-xv.x));
    float p1 = __fdividef(1.0f, 1.0f + __expf(-xv.y));
    int b0 = (int)(p0 * 15.0f); b0 = b0 > 14 ? 14 : b0;
    int b1 = (int)(p1 * 15.0f); b1 = b1 > 14 ? 14 : b1;
    acc[0][b0][tid] += p0 - tv.x;
    acc[1][b1][tid] += p1 - tv.y;
}

__global__ void __launch_bounds__(TPB, 7)
ece_fused(const float2* __restrict__ logits2, const float2* __restrict__ targets2,
          int n2, float* __restrict__ out, float inv_scale) {
    // acc[j][bin][tid], j = parity within the float2. class(2i+j) = 2*(i&7)+j
    // is loop-invariant per (thread, j) since the grid stride is a multiple
    // of 8. Lane stride 4B -> conflict-free LDS/STS.
    __shared__ float acc[2][NBINS][TPB];
    const int tid = threadIdx.x;
    #pragma unroll
    for (int b = 0; b < NBINS; b++) { acc[0][b][tid] = 0.0f; acc[1][b][tid] = 0.0f; }
    __syncthreads();

    const int stride = NBLK * TPB;
    int i = blockIdx.x * TPB + tid;

    for (; i + 3 * stride < n2; i += 4 * stride) {
        float2 x0 = logits2[i];
        float2 x1 = logits2[i + stride];
        float2 x2 = logits2[i + 2 * stride];
        float2 x3 = logits2[i + 3 * stride];
        float2 t0 = targets2[i];
        float2 t1 = targets2[i + stride];
        float2 t2 = targets2[i + 2 * stride];
        float2 t3 = targets2[i + 3 * stride];
        proc_pair(x0, t0, acc, tid);
        proc_pair(x1, t1, acc, tid);
        proc_pair(x2, t2, acc, tid);
        proc_pair(x3, t3, acc, tid);
    }
    for (; i < n2; i += stride) {
        proc_pair(logits2[i], targets2[i], acc, tid);
    }
    __syncthreads();

    // Fold 2*256 private slots into 240 cells. Cell = tid (< 240):
    // bin b = tid>>4, class c = tid&15 = 2q+j -> slots k*8+q, k=0..31.
    if (tid < NCELLS) {
        int b = tid >> 4;
        int c = tid & 15;
        int q = c >> 1;
        int j = c & 1;
        float s = 0.0f;
        #pragma unroll
        for (int k = 0; k < 32; k++) s += acc[j][b][k * 8 + q];
        g_partials[tid * NBLK + blockIdx.x] = s;
    }

    // Last-block tail: reduce the (L2-hot) partials in-kernel.
    __threadfence();
    __shared__ bool isLast;
    if (tid == 0)
        isLast = (atomicAdd(&g_ticket, 1u) == (unsigned)(NBLK - 1));
    __syncthreads();
    if (!isLast) return;

    __shared__ float warp_tot[TPB / 32];
    const int warp = tid >> 5;
    const int lane = tid & 31;
    float total = 0.0f;
    for (int cell = warp; cell < NCELLS; cell += TPB / 32) {
        const float4* row = (const float4*)&g_partials[cell * NBLK];  // 266 float4
        float s0 = 0.0f, s1 = 0.0f, s2 = 0.0f, s3 = 0.0f;
        int k = lane;
        #pragma unroll 8
        for (; k < NBLK / 4; k += 32) {
            float4 v = row[k];
            s0 += v.x; s1 += v.y; s2 += v.z; s3 += v.w;
        }
        float s = (s0 + s1) + (s2 + s3);
        #pragma unroll
        for (int off = 16; off > 0; off >>= 1)
            s += __shfl_xor_sync(0xffffffffu, s, off);
        if (lane == 0) total += fabsf(s);
    }
    if (lane == 0) warp_tot[warp] = total;
    __syncthreads();
    if (tid == 0) {
        float t = 0.0f;
        #pragma unroll
        for (int w = 0; w < TPB / 32; w++) t += warp_tot[w];
        out[0] = t * inv_scale;
        g_ticket = 0;   // reset for next graph replay
    }
}

extern "C" void kernel_launch(void* const* d_in, const int* in_sizes, int n_in,
                              void* d_out, int out_size) {
    const float2* logits2  = (const float2*)d_in[0];
    const float2* targets2 = (const float2*)d_in[1];
    float* out = (float*)d_out;
    const int n  = in_sizes[0];            // B*C = 33 554 432
    const int n2 = n >> 1;
    const float B = (float)(n / NCLS);

    // ECE = (sum over 240 cells of |sum(p - t)|) / B / NCELLS  (all nonempty)
    ece_fused<<<NBLK, TPB>>>(logits2, targets2, n2, out, 1.0f / (B * (float)NCELLS));
}

// round 10
// speedup vs baseline: 1.5466x; 1.5466x over previous
#include <cuda_runtime.h>

#define TPB    256
#define NBINS  15
#define NCLS   16
#define NCELLS (NBINS * NCLS)   // 240
#define NBLK1  1064             // 152 SMs * 7 blocks

// Per-block per-cell partials. Layout [cell][block] so kernel2 reads contiguously.
__device__ float        g_partials[NCELLS * NBLK1];
__device__ float        g_cell_abs[NCELLS];
__device__ unsigned int g_ticket = 0;

__device__ __forceinline__ void proc_pair(float2 xv, float2 tv,
                                          float (*acc)[NBINS][TPB], int tid) {
    float p0 = __fdividef(1.0f, 1.0f + __expf(-xv.x));
    float p1 = __fdividef(1.0f, 1.0f + __expf(-xv.y));
    int b0 = (int)(p0 * 15.0f); b0 = b0 > 14 ? 14 : b0;
    int b1 = (int)(p1 * 15.0f); b1 = b1 > 14 ? 14 : b1;
    acc[0][b0][tid] += p0 - tv.x;
    acc[1][b1][tid] += p1 - tv.y;
}

__global__ void __launch_bounds__(TPB, 7)
ece_accum(const float2* __restrict__ logits2, const float2* __restrict__ targets2, int n2) {
    // Private accumulators: acc[j][bin][tid], j = element parity within the
    // float2. class(element 2i+j) = 2*(i&7)+j, loop-invariant per (thread, j).
    // tid-major inner dim -> 4B lane stride -> conflict-free LDS/STS.
    __shared__ float acc[2][NBINS][TPB];
    const int tid = threadIdx.x;
    #pragma unroll
    for (int b = 0; b < NBINS; b++) { acc[0][b][tid] = 0.0f; acc[1][b][tid] = 0.0f; }
    __syncthreads();

    const int stride = NBLK1 * TPB;
    int i = blockIdx.x * TPB + tid;

    for (; i + 3 * stride < n2; i += 4 * stride) {
        float2 x0 = logits2[i];
        float2 x1 = logits2[i + stride];
        float2 x2 = logits2[i + 2 * stride];
        float2 x3 = logits2[i + 3 * stride];
        float2 t0 = targets2[i];
        float2 t1 = targets2[i + stride];
        float2 t2 = targets2[i + 2 * stride];
        float2 t3 = targets2[i + 3 * stride];
        proc_pair(x0, t0, acc, tid);
        proc_pair(x1, t1, acc, tid);
        proc_pair(x2, t2, acc, tid);
        proc_pair(x3, t3, acc, tid);
    }
    for (; i < n2; i += stride) {
        proc_pair(logits2[i], targets2[i], acc, tid);
    }
    __syncthreads();

    // Fold 2*256 private slots into 240 cells. Cell = tid (< 240):
    // bin b = tid>>4, class c = tid&15 = 2q+j -> slots k*8+q, k=0..31.
    if (tid < NCELLS) {
        int b = tid >> 4;
        int c = tid & 15;
        int q = c >> 1;
        int j = c & 1;
        float s = 0.0f;
        #pragma unroll
        for (int k = 0; k < 32; k++) s += acc[j][b][k * 8 + q];
        g_partials[tid * NBLK1 + blockIdx.x] = s;
    }
}

// Kernel 2: one block per cell reduces its 1064-float row (L2-hot, float4,
// coalesced); the last block to finish folds the 240 |sums| into the scalar.
// Fixed summation order everywhere -> deterministic across replays.
__global__ void __launch_bounds__(TPB, 1)
ece_tail(float* __restrict__ out, float inv_scale) {
    __shared__ float red[TPB];
    const int cell = blockIdx.x;
    const int tid = threadIdx.x;

    const float4* row = (const float4*)&g_partials[cell * NBLK1];  // 266 float4
    float s0 = 0.0f, s1 = 0.0f, s2 = 0.0f, s3 = 0.0f;
    #pragma unroll
    for (int k = tid; k < NBLK1 / 4; k += TPB) {
        float4 v = row[k];
        s0 += v.x; s1 += v.y; s2 += v.z; s3 += v.w;
    }
    red[tid] = (s0 + s1) + (s2 + s3);
    __syncthreads();
    #pragma unroll
    for (int s = TPB / 2; s > 0; s >>= 1) {
        if (tid < s) red[tid] += red[tid + s];
        __syncthreads();
    }
    if (tid == 0) g_cell_abs[cell] = fabsf(red[0]);

    // Last block folds the 240 cell values.
    __threadfence();
    __shared__ bool isLast;
    if (tid == 0)
        isLast = (atomicAdd(&g_ticket, 1u) == (unsigned)(NCELLS - 1));
    __syncthreads();
    if (!isLast) return;

    float v = (tid < NCELLS) ? g_cell_abs[tid] : 0.0f;
    red[tid] = v;
    __syncthreads();
    #pragma unroll
    for (int s = TPB / 2; s > 0; s >>= 1) {
        if (tid < s) red[tid] += red[tid + s];
        __syncthreads();
    }
    if (tid == 0) {
        out[0] = red[0] * inv_scale;
        g_ticket = 0;   // reset for next graph replay
    }
}

extern "C" void kernel_launch(void* const* d_in, const int* in_sizes, int n_in,
                              void* d_out, int out_size) {
    const float2* logits2  = (const float2*)d_in[0];
    const float2* targets2 = (const float2*)d_in[1];
    float* out = (float*)d_out;
    const int n  = in_sizes[0];            // B*C = 33 554 432
    const int n2 = n >> 1;
    const float B = (float)(n / NCLS);

    ece_accum<<<NBLK1, TPB>>>(logits2, targets2, n2);
    // ECE = (sum over 240 cells of |sum(p - t)|) / B / NCELLS  (all nonempty)
    ece_tail<<<NCELLS, TPB>>>(out, 1.0f / (B * (float)NCELLS));
}